// round 1
// baseline (speedup 1.0000x reference)
#include <cuda_runtime.h>

#define BB   32
#define C1   64
#define GG   256
#define HW   122
#define W0IN 128

// ---------------- scratch (static __device__: allocation-free) ----------------
__device__ float g_feat[BB * C1 * HW * HW];        // ~122 MB
__device__ float g_i2s[BB * GG * HW * HW];         // ~488 MB (gates incl. both biases)
__device__ float g_h0[BB * C1 * HW];
__device__ float g_h1[BB * C1 * HW];
__device__ float g_c [BB * C1 * HW];

// ---------------- math helpers ----------------
__device__ __forceinline__ float tanha(float x) {
    float y;
    asm("tanh.approx.f32 %0, %1;" : "=f"(y) : "f"(x));
    return y;
}
__device__ __forceinline__ float sigmf(float x) {
    return 0.5f * tanha(0.5f * x) + 0.5f;
}

// ---------------- zero the recurrent state ----------------
__global__ void init_state_kernel() {
    int n = BB * C1 * HW;
    for (int i = blockIdx.x * blockDim.x + threadIdx.x; i < n; i += gridDim.x * blockDim.x) {
        g_h0[i] = 0.f; g_h1[i] = 0.f; g_c[i] = 0.f;
    }
}

// ---------------- conv1: 7x7 valid, [B,1,128,128] -> [B,64,122,122] ----------------
__global__ __launch_bounds__(256) void conv1_kernel(
    const float* __restrict__ x, const float* __restrict__ w1, const float* __restrict__ b1)
{
    __shared__ float xs[7][136];      // 7 input rows, padded
    __shared__ float ws[C1 * 49];
    __shared__ float bs[C1];

    int bh = blockIdx.x;
    int b = bh / HW, h = bh % HW;
    int t = threadIdx.x;

    for (int i = t; i < C1 * 49; i += 256) ws[i] = w1[i];
    if (t < C1) bs[t] = b1[t];
    for (int i = t; i < 7 * 136; i += 256) {
        int r = i / 136, cw = i % 136;
        xs[r][cw] = (cw < W0IN) ? x[(b * W0IN + (h + r)) * W0IN + cw] : 0.f;
    }
    __syncthreads();

    // tasks: 64 channels x 32 w-tiles (4 wide). warp lanes span w-tiles -> broadcast weights.
    for (int task = t; task < C1 * 32; task += 256) {
        int c = task >> 5;
        int wt = task & 31;
        int w0 = wt * 4;
        float a0 = 0.f, a1 = 0.f, a2 = 0.f, a3 = 0.f;
#pragma unroll
        for (int kh = 0; kh < 7; kh++) {
            float4 va = *(const float4*)&xs[kh][w0];
            float4 vb = *(const float4*)&xs[kh][w0 + 4];
            float2 vc = *(const float2*)&xs[kh][w0 + 8];
            float f[10] = {va.x, va.y, va.z, va.w, vb.x, vb.y, vb.z, vb.w, vc.x, vc.y};
            const float* wr = &ws[c * 49 + kh * 7];
#pragma unroll
            for (int kw = 0; kw < 7; kw++) {
                float wv = wr[kw];
                a0 += wv * f[kw];
                a1 += wv * f[kw + 1];
                a2 += wv * f[kw + 2];
                a3 += wv * f[kw + 3];
            }
        }
        float bb = bs[c];
        int base = ((b * C1 + c) * HW + h) * HW + w0;
        if (w0 + 0 < HW) g_feat[base + 0] = a0 + bb;
        if (w0 + 1 < HW) g_feat[base + 1] = a1 + bb;
        if (w0 + 2 < HW) g_feat[base + 2] = a2 + bb;
        if (w0 + 3 < HW) g_feat[base + 3] = a3 + bb;
    }
}

// ---------------- i2s: (1,3) conv SAME-width, feat -> gates [B,256,122,122] ----------------
// One CTA per (b, h, half). Stores gates with (i2s_b + s2s_b) folded in.
__global__ __launch_bounds__(256) void i2s_kernel(
    const float* __restrict__ w, const float* __restrict__ bi, const float* __restrict__ bs2)
{
    extern __shared__ float sm[];
    float* fp = sm;                        // [64][124] padded feat row (+8 slack)
    float* ws = sm + C1 * 124 + 8;         // [128][192]
    float* bc = ws + 128 * 192;            // [128]

    int bx = blockIdx.x;
    int half = bx & 1;
    int bh = bx >> 1;
    int b = bh / HW, h = bh % HW;
    int t = threadIdx.x;

    for (int i = t; i < C1 * 124; i += 256) {
        int c = i / 124, cw = i % 124;
        fp[i] = (cw >= 1 && cw <= HW) ? g_feat[((b * C1 + c) * HW + h) * HW + (cw - 1)] : 0.f;
    }
    if (t < 8) fp[C1 * 124 + t] = 0.f;   // slack pad
    for (int i = t; i < 128 * 192; i += 256) ws[i] = w[(half * 128) * 192 + i];
    if (t < 128) {
        int og = half * 128 + t;
        bc[t] = bi[og] + bs2[og];
    }
    __syncthreads();

    int wt = t & 31;          // warp lane = w-tile -> weight loads are warp-uniform
    int rt0 = t >> 5;         // 0..7
    int w0 = wt * 4;
    bool active = (w0 < HW);

    for (int pass = 0; pass < 2; pass++) {
        int oc0 = (rt0 + 8 * pass) * 8;
        float acc[8][4] = {};
        if (active) {
#pragma unroll 4
            for (int c = 0; c < C1; c++) {
                const float* fr = &fp[c * 124 + w0];
                float4 va = *(const float4*)fr;
                float2 vb = *(const float2*)(fr + 4);
                float f[6] = {va.x, va.y, va.z, va.w, vb.x, vb.y};
                const float* wr = &ws[oc0 * 192 + c * 3];
#pragma unroll
                for (int dx = 0; dx < 3; dx++) {
#pragma unroll
                    for (int i = 0; i < 8; i++) {
                        float wv = wr[i * 192 + dx];
                        acc[i][0] += wv * f[dx];
                        acc[i][1] += wv * f[dx + 1];
                        acc[i][2] += wv * f[dx + 2];
                        acc[i][3] += wv * f[dx + 3];
                    }
                }
            }
#pragma unroll
            for (int i = 0; i < 8; i++) {
                int ocl = oc0 + i;
                int og = half * 128 + ocl;
                float bb = bc[ocl];
                int base = ((b * GG + og) * HW + h) * HW + w0;
#pragma unroll
                for (int j = 0; j < 4; j++)
                    if (w0 + j < HW) g_i2s[base + j] = acc[i][j] + bb;
            }
        }
    }
}

// ---------------- scan step: s2s conv + LSTM for one row r ----------------
// Grid: (b, 8-hidden-channel block) = 256 CTAs, 256 threads.
__global__ __launch_bounds__(256) void step_kernel(
    const float* __restrict__ ws2, float* __restrict__ out, int r)
{
    extern __shared__ float sm[];
    float* hp = sm;                    // [64][124] padded h_prev (+8 slack)
    float* ws = sm + C1 * 124 + 8;     // [4 gates][8 hc][192]

    int bx = blockIdx.x;
    int b = bx >> 3;
    int hc0 = (bx & 7) * 8;
    int t = threadIdx.x;

    const float* hsrc = (r & 1) ? g_h1 : g_h0;
    float*       hdst = (r & 1) ? g_h0 : g_h1;

    for (int i = t; i < C1 * 124; i += 256) {
        int c = i / 124, cw = i % 124;
        hp[i] = (cw >= 1 && cw <= HW) ? hsrc[(b * C1 + c) * HW + (cw - 1)] : 0.f;
    }
    if (t < 8) hp[C1 * 124 + t] = 0.f;
    for (int i = t; i < 32 * 192; i += 256) {
        int row = i / 192, k = i % 192;
        int gate = row >> 3, hh = row & 7;
        ws[i] = ws2[(gate * 64 + hc0 + hh) * 192 + k];
    }
    __syncthreads();

    int wt = t & 31;          // lane = w-tile
    int hh = t >> 5;          // 0..7
    int hc = hc0 + hh;
    int w0 = wt * 4;
    if (w0 >= HW) return;

    float acc[4][4] = {};
#pragma unroll 4
    for (int c = 0; c < C1; c++) {
        const float* fr = &hp[c * 124 + w0];
        float4 va = *(const float4*)fr;
        float2 vb = *(const float2*)(fr + 4);
        float f[6] = {va.x, va.y, va.z, va.w, vb.x, vb.y};
        const float* wr = &ws[hh * 192 + c * 3];
#pragma unroll
        for (int dx = 0; dx < 3; dx++) {
#pragma unroll
            for (int g = 0; g < 4; g++) {
                float wv = wr[g * 1536 + dx];     // gate stride = 8*192
                acc[g][0] += wv * f[dx];
                acc[g][1] += wv * f[dx + 1];
                acc[g][2] += wv * f[dx + 2];
                acc[g][3] += wv * f[dx + 3];
            }
        }
    }

    int i2sbase = (b * GG * HW + r) * HW;   // + og*HW*HW + w
#pragma unroll
    for (int j = 0; j < 4; j++) {
        int wp = w0 + j;
        if (wp >= HW) continue;
        float go = acc[0][j] + g_i2s[i2sbase + (0   + hc) * HW * HW + wp];
        float gf = acc[1][j] + g_i2s[i2sbase + (64  + hc) * HW * HW + wp];
        float gi = acc[2][j] + g_i2s[i2sbase + (128 + hc) * HW * HW + wp];
        float gg = acc[3][j] + g_i2s[i2sbase + (192 + hc) * HW * HW + wp];

        int sidx = (b * C1 + hc) * HW + wp;
        float cp = g_c[sidx];
        float cn = sigmf(gf) * cp + sigmf(gi) * tanha(gg);
        float hv = sigmf(go) * tanha(cn);
        g_c[sidx]  = cn;
        hdst[sidx] = hv;
        out[((b * C1 + hc) * HW + r) * HW + wp] = hv;
    }
}

// ---------------- launch ----------------
extern "C" void kernel_launch(void* const* d_in, const int* in_sizes, int n_in,
                              void* d_out, int out_size)
{
    const float* x   = (const float*)d_in[0];
    const float* c1w = (const float*)d_in[1];
    const float* c1b = (const float*)d_in[2];
    const float* i2w = (const float*)d_in[3];
    const float* i2b = (const float*)d_in[4];
    const float* s2w = (const float*)d_in[5];
    const float* s2b = (const float*)d_in[6];
    float* out = (float*)d_out;

    const int i2s_smem  = (C1 * 124 + 8 + 128 * 192 + 128) * sizeof(float);   // ~130.6 KB
    const int step_smem = (C1 * 124 + 8 + 32 * 192) * sizeof(float);          // ~56.4 KB
    cudaFuncSetAttribute(i2s_kernel,  cudaFuncAttributeMaxDynamicSharedMemorySize, i2s_smem);
    cudaFuncSetAttribute(step_kernel, cudaFuncAttributeMaxDynamicSharedMemorySize, step_smem);

    init_state_kernel<<<256, 256>>>();
    conv1_kernel<<<BB * HW, 256>>>(x, c1w, c1b);
    i2s_kernel<<<BB * HW * 2, 256, i2s_smem>>>(i2w, i2b, s2b);
    for (int r = 0; r < HW; r++)
        step_kernel<<<BB * 8, 256, step_smem>>>(s2w, out, r);
}

// round 2
// speedup vs baseline: 1.0291x; 1.0291x over previous
#include <cuda_runtime.h>

#define BB   32
#define C1   64
#define GG   256
#define HW   122
#define W0IN 128
#define CLU  8

typedef unsigned long long u64;

// ---------------- scratch (static __device__: allocation-free) ----------------
__device__ float g_feat[BB * C1 * HW * HW];        // ~122 MB
__device__ float g_i2s[BB * GG * HW * HW];         // ~488 MB (gates incl. both biases)
__device__ float g_h0[BB * C1 * HW];
__device__ float g_h1[BB * C1 * HW];

// ---------------- math helpers ----------------
__device__ __forceinline__ float tanha(float x) {
    float y;
    asm("tanh.approx.f32 %0, %1;" : "=f"(y) : "f"(x));
    return y;
}
__device__ __forceinline__ float sigmf(float x) {
    return 0.5f * tanha(0.5f * x) + 0.5f;
}
__device__ __forceinline__ u64 pk2(float lo, float hi) {
    u64 r;
    asm("mov.b64 %0, {%1, %2};" : "=l"(r) : "f"(lo), "f"(hi));
    return r;
}
__device__ __forceinline__ void fma2(u64& d, u64 a, u64 b) {
    asm("fma.rn.f32x2 %0, %1, %2, %0;" : "+l"(d) : "l"(a), "l"(b));
}
__device__ __forceinline__ void unpk2(u64 v, float& lo, float& hi) {
    asm("mov.b64 {%0, %1}, %2;" : "=f"(lo), "=f"(hi) : "l"(v));
}

// ---------------- conv1: 7x7 valid, [B,1,128,128] -> [B,64,122,122] ----------------
__global__ __launch_bounds__(256) void conv1_kernel(
    const float* __restrict__ x, const float* __restrict__ w1, const float* __restrict__ b1)
{
    __shared__ float xs[7][136];
    __shared__ float ws[C1 * 49];
    __shared__ float bs[C1];

    int bh = blockIdx.x;
    int b = bh / HW, h = bh % HW;
    int t = threadIdx.x;

    for (int i = t; i < C1 * 49; i += 256) ws[i] = w1[i];
    if (t < C1) bs[t] = b1[t];
    for (int i = t; i < 7 * 136; i += 256) {
        int r = i / 136, cw = i % 136;
        xs[r][cw] = (cw < W0IN) ? x[(b * W0IN + (h + r)) * W0IN + cw] : 0.f;
    }
    __syncthreads();

    for (int task = t; task < C1 * 32; task += 256) {
        int c = task >> 5;
        int wt = task & 31;
        int w0 = wt * 4;
        float a0 = 0.f, a1 = 0.f, a2 = 0.f, a3 = 0.f;
#pragma unroll
        for (int kh = 0; kh < 7; kh++) {
            float4 va = *(const float4*)&xs[kh][w0];
            float4 vb = *(const float4*)&xs[kh][w0 + 4];
            float2 vc = *(const float2*)&xs[kh][w0 + 8];
            float f[10] = {va.x, va.y, va.z, va.w, vb.x, vb.y, vb.z, vb.w, vc.x, vc.y};
            const float* wr = &ws[c * 49 + kh * 7];
#pragma unroll
            for (int kw = 0; kw < 7; kw++) {
                float wv = wr[kw];
                a0 += wv * f[kw];
                a1 += wv * f[kw + 1];
                a2 += wv * f[kw + 2];
                a3 += wv * f[kw + 3];
            }
        }
        float bb = bs[c];
        int base = ((b * C1 + c) * HW + h) * HW + w0;
        if (w0 + 0 < HW) g_feat[base + 0] = a0 + bb;
        if (w0 + 1 < HW) g_feat[base + 1] = a1 + bb;
        if (w0 + 2 < HW) g_feat[base + 2] = a2 + bb;
        if (w0 + 3 < HW) g_feat[base + 3] = a3 + bb;
    }
}

// ---------------- i2s: (1,3) conv SAME-width, f32x2 inner loop ----------------
__global__ __launch_bounds__(256) void i2s_kernel(
    const float* __restrict__ w, const float* __restrict__ bi, const float* __restrict__ bs2)
{
    extern __shared__ float sm[];
    float* fp = sm;                        // [64][124] padded feat row
    float* ws = sm + C1 * 124 + 8;         // [128][192]
    float* bc = ws + 128 * 192;            // [128]

    int bx = blockIdx.x;
    int half = bx & 1;
    int bh = bx >> 1;
    int b = bh / HW, h = bh % HW;
    int t = threadIdx.x;

    for (int i = t; i < C1 * 124; i += 256) {
        int c = i / 124, cw = i % 124;
        fp[i] = (cw >= 1 && cw <= HW) ? g_feat[((b * C1 + c) * HW + h) * HW + (cw - 1)] : 0.f;
    }
    if (t < 8) fp[C1 * 124 + t] = 0.f;
    for (int i = t; i < 128 * 192; i += 256) ws[i] = w[(half * 128) * 192 + i];
    if (t < 128) {
        int og = half * 128 + t;
        bc[t] = bi[og] + bs2[og];
    }
    __syncthreads();

    int wt = t & 31;
    int rt0 = t >> 5;
    int w0 = wt * 4;
    bool active = (w0 < HW);

    for (int pass = 0; pass < 2; pass++) {
        int oc0 = (rt0 + 8 * pass) * 8;
        if (active) {
            u64 aA[8], aB[8];
#pragma unroll
            for (int i = 0; i < 8; i++) { aA[i] = 0ull; aB[i] = 0ull; }
#pragma unroll 2
            for (int c = 0; c < C1; c++) {
                const float* fr = &fp[c * 124 + w0];
                float4 va = *(const float4*)fr;
                float2 vb = *(const float2*)(fr + 4);
                u64 P0 = pk2(va.x, va.y), P1 = pk2(va.y, va.z), P2 = pk2(va.z, va.w);
                u64 P3 = pk2(va.w, vb.x), P4 = pk2(vb.x, vb.y);
                const float* wr = &ws[oc0 * 192 + c * 3];
#pragma unroll
                for (int i = 0; i < 8; i++) {
                    float wv0 = wr[i * 192 + 0];
                    float wv1 = wr[i * 192 + 1];
                    float wv2 = wr[i * 192 + 2];
                    u64 s0 = pk2(wv0, wv0), s1 = pk2(wv1, wv1), s2 = pk2(wv2, wv2);
                    fma2(aA[i], s0, P0);  fma2(aB[i], s0, P2);
                    fma2(aA[i], s1, P1);  fma2(aB[i], s1, P3);
                    fma2(aA[i], s2, P2);  fma2(aB[i], s2, P4);
                }
            }
#pragma unroll
            for (int i = 0; i < 8; i++) {
                int ocl = oc0 + i;
                int og = half * 128 + ocl;
                float bb = bc[ocl];
                float r0, r1, r2, r3;
                unpk2(aA[i], r0, r1);
                unpk2(aB[i], r2, r3);
                int base = ((b * GG + og) * HW + h) * HW + w0;
                if (w0 + 0 < HW) g_i2s[base + 0] = r0 + bb;
                if (w0 + 1 < HW) g_i2s[base + 1] = r1 + bb;
                if (w0 + 2 < HW) g_i2s[base + 2] = r2 + bb;
                if (w0 + 3 < HW) g_i2s[base + 3] = r3 + bb;
            }
        }
    }
}

// ---------------- persistent scan: 32 clusters x 8 CTAs, 122 rows ----------------
// CTA = (batch b, 8 hidden channels hc0..hc0+7). Weights resident in smem,
// c state in registers, h exchanged through L2 with cluster barriers.
__global__ __launch_bounds__(256, 2) __cluster_dims__(CLU, 1, 1)
void scan_kernel(const float* __restrict__ ws2, float* __restrict__ out)
{
    extern __shared__ float sm[];
    float* hst = sm;                 // [64][124] padded h_prev staging
    float* ws  = sm + C1 * 124;      // [4 gates][8 hh][192]

    int t  = threadIdx.x;
    int bx = blockIdx.x;
    int b  = bx / CLU;               // cluster = batch
    int jr = bx % CLU;               // rank in cluster
    int hc0 = jr * 8;

    // resident weights: [gate][hh][192]
    for (int i = t; i < 32 * 192; i += 256) {
        int row = i / 192, k = i % 192;
        int gate = row >> 3, hh = row & 7;
        ws[i] = ws2[(gate * 64 + hc0 + hh) * 192 + k];
    }

    int wid  = t >> 5;               // warp -> hidden channel within CTA
    int lane = t & 31;               // lane -> 4-wide w tile
    int hc   = hc0 + wid;
    int w0   = lane * 4;
    bool active = (w0 < HW);         // lanes 0..30

    float cst[4] = {0.f, 0.f, 0.f, 0.f};
    const int HW2 = HW * HW;

    for (int r = 0; r < HW; r++) {
        const float* hsrc = (r & 1) ? g_h1 : g_h0;
        float*       hdst = (r & 1) ? g_h0 : g_h1;

        // stage h_prev (all 64 channels of this batch) into local smem
        if (r == 0) {
            for (int i = t; i < C1 * 124; i += 256) hst[i] = 0.f;
        } else {
            for (int i = t; i < C1 * 124; i += 256) {
                int c = i / 124, cw = i % 124;
                float v = 0.f;
                if (cw >= 1 && cw <= HW) v = __ldcg(&hsrc[(b * C1 + c) * HW + (cw - 1)]);
                hst[i] = v;
            }
        }
        __syncthreads();

        if (active) {
            u64 aA[4], aB[4];
#pragma unroll
            for (int g = 0; g < 4; g++) { aA[g] = 0ull; aB[g] = 0ull; }
#pragma unroll 4
            for (int c = 0; c < C1; c++) {
                const float* fr = &hst[c * 124 + w0];
                float4 va = *(const float4*)fr;
                float2 vb = *(const float2*)(fr + 4);
                u64 P0 = pk2(va.x, va.y), P1 = pk2(va.y, va.z), P2 = pk2(va.z, va.w);
                u64 P3 = pk2(va.w, vb.x), P4 = pk2(vb.x, vb.y);
                const float* wr = &ws[wid * 192 + c * 3];
#pragma unroll
                for (int g = 0; g < 4; g++) {
                    float wv0 = wr[g * 1536 + 0];
                    float wv1 = wr[g * 1536 + 1];
                    float wv2 = wr[g * 1536 + 2];
                    u64 s0 = pk2(wv0, wv0), s1 = pk2(wv1, wv1), s2 = pk2(wv2, wv2);
                    fma2(aA[g], s0, P0);  fma2(aB[g], s0, P2);
                    fma2(aA[g], s1, P1);  fma2(aB[g], s1, P3);
                    fma2(aA[g], s2, P2);  fma2(aB[g], s2, P4);
                }
            }

            float ga[4][4];
#pragma unroll
            for (int g = 0; g < 4; g++) {
                unpk2(aA[g], ga[g][0], ga[g][1]);
                unpk2(aB[g], ga[g][2], ga[g][3]);
            }

            int gbase = (b * GG) * HW2 + r * HW;
#pragma unroll
            for (int j = 0; j < 4; j++) {
                int wp = w0 + j;
                if (wp >= HW) continue;
                float go = ga[0][j] + g_i2s[gbase + (0   + hc) * HW2 + wp];
                float gf = ga[1][j] + g_i2s[gbase + (64  + hc) * HW2 + wp];
                float gi = ga[2][j] + g_i2s[gbase + (128 + hc) * HW2 + wp];
                float gg = ga[3][j] + g_i2s[gbase + (192 + hc) * HW2 + wp];

                float cn = sigmf(gf) * cst[j] + sigmf(gi) * tanha(gg);
                float hv = sigmf(go) * tanha(cn);
                cst[j] = cn;
                __stcg(&hdst[(b * C1 + hc) * HW + wp], hv);
                out[((b * C1 + hc) * HW + r) * HW + wp] = hv;
            }
        }

        // release h writes / acquire peers' h for the next row
        asm volatile("barrier.cluster.arrive.aligned;" ::: "memory");
        asm volatile("barrier.cluster.wait.aligned;"   ::: "memory");
    }
}

// ---------------- launch ----------------
extern "C" void kernel_launch(void* const* d_in, const int* in_sizes, int n_in,
                              void* d_out, int out_size)
{
    const float* x   = (const float*)d_in[0];
    const float* c1w = (const float*)d_in[1];
    const float* c1b = (const float*)d_in[2];
    const float* i2w = (const float*)d_in[3];
    const float* i2b = (const float*)d_in[4];
    const float* s2w = (const float*)d_in[5];
    const float* s2b = (const float*)d_in[6];
    float* out = (float*)d_out;

    const int i2s_smem  = (C1 * 124 + 8 + 128 * 192 + 128) * sizeof(float);   // ~130.6 KB
    const int scan_smem = (C1 * 124 + 32 * 192) * sizeof(float);              // 56320 B
    cudaFuncSetAttribute(i2s_kernel,  cudaFuncAttributeMaxDynamicSharedMemorySize, i2s_smem);
    cudaFuncSetAttribute(scan_kernel, cudaFuncAttributeMaxDynamicSharedMemorySize, scan_smem);

    conv1_kernel<<<BB * HW, 256>>>(x, c1w, c1b);
    i2s_kernel<<<BB * HW * 2, 256, i2s_smem>>>(i2w, i2b, s2b);
    scan_kernel<<<BB * CLU, 256, scan_smem>>>(s2w, out);
}